// round 17
// baseline (speedup 1.0000x reference)
#include <cuda_runtime.h>
#include <cstdint>

// Problem constants
#define B_  32
#define C_  128
#define H_  36
#define W_  100
#define KW  9

// Scratch ping-pong buffers (device globals: no runtime allocation allowed)
__device__ float g_buf0[(size_t)B_ * C_ * H_ * W_];
__device__ float g_buf1[(size_t)B_ * C_ * H_ * W_];
__device__ float g_buf2[(size_t)B_ * C_ * H_ * W_];

#define CLUSTER_ARRIVE() \
    asm volatile("barrier.cluster.arrive.aligned;" ::: "memory")
#define CLUSTER_WAIT() \
    asm volatile("barrier.cluster.wait.aligned;" ::: "memory")

#define CP_ASYNC16(saddr, gptr) \
    asm volatile("cp.async.cg.shared.global [%0], [%1], 16;" \
                 :: "r"(saddr), "l"(gptr))
#define CP_ASYNC_COMMIT() asm volatile("cp.async.commit_group;" ::: "memory")
#define CP_ASYNC_WAIT0()  asm volatile("cp.async.wait_group 0;" ::: "memory")

// Per-16-ci-block skew (in floats). Non-monotonic -> blocks carry stride pads.
static __device__ __host__ __forceinline__ int SKF(int u) {
    return (((u >> 1) & 1) << 2) + ((u >> 2) << 4) + ((u & 1) << 3);
}

#define FMA2(d, a, b, c) \
    asm("fma.rn.f32x2 %0, %1, %2, %3;" : "=l"(d) : "l"(a), "l"(b), "l"(c))
#define PACK2(d, v) \
    asm("mov.b64 %0, {%1, %1};" : "=l"(d) : "f"(v))
#define UNPACK2(lo, hi, p) \
    asm("mov.b64 {%0, %1}, %2;" : "=f"(lo), "=f"(hi) : "l"(p))

// One SCNN message-passing pass over a [B, C, S, L] tensor.
// Cluster of 4 CTAs per batch; CTA g owns output channels [32g, 32g+32).
// Weights live in SMEM all pass. Each thread: COW co x 8 w outputs.
// Software-pipelined exchange: phase A convolves the CTA's OWN 32 input
// channels (already local) BEFORE the cluster wait; the peer reload
// (cp.async) and phase B (96 ci) follow. Lanes take ci strided by CI_SPLIT;
// WROW=292 (=4 mod 32) keeps strided weight reads bank-conflict-free.
template <int S, int L, int CI_SPLIT, int BLOCK, int COW, bool TRANS>
__global__ void __launch_bounds__(BLOCK, 1) __cluster_dims__(4, 1, 1)
scnn_pass(const float* __restrict__ in, const float* __restrict__ wts,
          float* __restrict__ out, int rev, float* __restrict__ tout)
{
    constexpr int PS    = L + 16;        // padded row stride (4 left, 12 right)
    constexpr int L4    = L / 4;
    constexpr int NWT   = (L + 7) / 8;   // 8-wide w tiles (last may be partial)
    constexpr int CHS   = S * L;
    constexpr int NPAIR = COW / 2;       // f32x2 co-pairs per thread
    constexpr int WROW  = KW * 32 + 4;   // 292: =4 mod 32 -> strided lanes on
                                         // distinct bank quads
    constexpr int WBLK  = 16 * WROW + 32;
    constexpr int PBLK  = 16 * PS + 32;
    constexpr int WFL   = 8 * WBLK + 32;
    constexpr int PPF   = 8 * PBLK + 32;
    constexpr int CNTA  = 32 / CI_SPLIT;  // own-ci iters per lane
    constexpr int CNTB  = 96 / CI_SPLIT;  // peer-ci iters per lane

    extern __shared__ float smem[];
    float* wsm = smem;            // [blk pad+skew][ci16][k][co32]
    float* pp  = smem + WFL;      // [blk pad+skew][c16][PS]
    float* xsm = pp + PPF;        // [32 co][L] staged skip-connection row

    const int tid = threadIdx.x;
    const int g   = blockIdx.x;
    const int b   = blockIdx.y;
    const int co0 = g * 32;

    const float* inB  = in  + (size_t)b * C_ * CHS;
    float*       outB = out + (size_t)b * C_ * CHS;
    float*       toutB = TRANS ? tout + (size_t)b * C_ * CHS : nullptr;

    uint32_t sbase;
    asm("{ .reg .u64 t; cvta.to.shared.u64 t, %1; cvt.u32.u64 %0, t; }"
        : "=r"(sbase) : "l"(smem));

    #define PP_OFF(c)  (((c) >> 4) * PBLK + ((c) & 15) * PS + SKF((c) >> 4))
    #define W_OFF(ci)  (((ci) >> 4) * WBLK + ((ci) & 15) * WROW + SKF((ci) >> 4))

    // ---- load weight slice w[co0..co0+31][ci][k] into skewed smem ----
    {
        const float* wg = wts + (size_t)co0 * (C_ * KW);
        for (int idx = tid; idx < 32 * C_ * KW; idx += BLOCK) {
            int col = idx / (C_ * KW);
            int r   = idx - col * (C_ * KW);      // ci*9 + k
            int ci  = r / KW;
            int k   = r - ci * KW;
            wsm[W_OFF(ci) + k * 32 + col] = wg[idx];
        }
    }
    for (int idx = tid; idx < PPF; idx += BLOCK) pp[idx] = 0.0f;

    // ---- thread -> (COW co) x (8 consecutive w), ci split ----
    const int  task = tid / CI_SPLIT;
    const int  ciq  = tid % CI_SPLIT;
    const int  wt   = task % NWT;
    const int  cot  = task / NWT;
    const int  w0   = wt * 8;
    const int  colB = cot * COW;
    const bool st2  = (w0 + 4 < L);

    // epilogue roles: lane ciq = aa*2+hh writes float4 (co colB+aa, half hh)
    const int  aa   = ciq >> 1;
    const int  hh   = ciq & 1;
    const bool doO  = (ciq < 2 * COW) && (hh == 0 || st2);
    const int  tl   = (CI_SPLIT >= 8) ? (ciq - 4) : ciq;
    const bool doT  = TRANS && (tl >= 0) && (tl < 4);

    __syncthreads();

    for (int step = 0; step < S; ++step) {
        const int    p      = rev ? (S - 1 - step) : step;
        const size_t rowOff = (size_t)p * L;
        const int    pn     = rev ? (p - 1) : (p + 1);   // next step's row
        const int    pr     = rev ? (p + 1) : (p - 1);   // previous row

        if (step == 0) {
            for (int idx = tid; idx < 32 * L4; idx += BLOCK) {
                int c = idx / L4, j = idx - c * L4;
                const size_t o = (size_t)(co0 + c) * CHS + rowOff + 4 * j;
                *reinterpret_cast<float4*>(outB + o) =
                    *reinterpret_cast<const float4*>(inB + o);
            }
            if (TRANS) {   // transposed copy of row p (own co slice)
                for (int idx = tid; idx < 32 * L; idx += BLOCK) {
                    int c = idx / L, w = idx - c * L;
                    toutB[(size_t)(co0 + c) * CHS + (size_t)w * S + p] =
                        inB[(size_t)(co0 + c) * CHS + rowOff + w];
                }
            }
            // pp <- in row p (ALL channels; out row == in row here)
            for (int idx = tid; idx < C_ * L4; idx += BLOCK) {
                int c = idx / L4, j = idx - c * L4;
                const float4 v = *reinterpret_cast<const float4*>(
                    inB + (size_t)c * CHS + rowOff + 4 * j);
                *reinterpret_cast<float4*>(&pp[PP_OFF(c) + 4 + 4 * j]) = v;
            }
            // stage next row's skip-connection input (own co slice)
            if (tid < 32 * L4) {
                int c = tid / L4, j = tid - c * L4;
                *reinterpret_cast<float4*>(&xsm[c * L + 4 * j]) =
                    *reinterpret_cast<const float4*>(
                        inB + (size_t)(co0 + c) * CHS + (size_t)pn * L + 4 * j);
            }
            if (step + 1 < S) CLUSTER_ARRIVE();   // pairs with step 1's wait
            __syncthreads();
        } else {
            unsigned long long acc2[NPAIR][8];
            #pragma unroll
            for (int pr2 = 0; pr2 < NPAIR; ++pr2)
                #pragma unroll
                for (int j = 0; j < 8; ++j) acc2[pr2][j] = 0ull;

            // generic strided convolution accumulator: lane handles
            // ci = ciStart, ciStart+CI_SPLIT, ... (cnt iters, mod 128)
            auto conv_run = [&](int ciStart, int cnt) {
                int ci = ciStart;
                int ub = ci >> 4, r = ci & 15;
                const float* prow = pp + ub * PBLK + r * PS + SKF(ub) + w0;
                uint32_t wadr = sbase +
                    (uint32_t)(ub * WBLK + r * WROW + SKF(ub) + colB) * 4u;
                float4 va = *reinterpret_cast<const float4*>(prow);
                float4 vb = *reinterpret_cast<const float4*>(prow + 4);
                float4 vc = *reinterpret_cast<const float4*>(prow + 8);
                float4 vd = *reinterpret_cast<const float4*>(prow + 12);
                #pragma unroll 4
                for (int i = 0; i < cnt; ++i) {
                    unsigned long long vp[16];
                    PACK2(vp[0],  va.x); PACK2(vp[1],  va.y);
                    PACK2(vp[2],  va.z); PACK2(vp[3],  va.w);
                    PACK2(vp[4],  vb.x); PACK2(vp[5],  vb.y);
                    PACK2(vp[6],  vb.z); PACK2(vp[7],  vb.w);
                    PACK2(vp[8],  vc.x); PACK2(vp[9],  vc.y);
                    PACK2(vp[10], vc.z); PACK2(vp[11], vc.w);
                    PACK2(vp[12], vd.x); PACK2(vp[13], vd.y);
                    PACK2(vp[14], vd.z); PACK2(vp[15], vd.w);

                    // next ci's addresses; prefetch its p row during FMAs
                    const int cin = (ci + CI_SPLIT) & (C_ - 1);
                    const int ubn = cin >> 4, rn = cin & 15;
                    const float* prown =
                        pp + ubn * PBLK + rn * PS + SKF(ubn) + w0;
                    if (i + 1 < cnt) {
                        va = *reinterpret_cast<const float4*>(prown);
                        vb = *reinterpret_cast<const float4*>(prown + 4);
                        vc = *reinterpret_cast<const float4*>(prown + 8);
                        vd = *reinterpret_cast<const float4*>(prown + 12);
                    }

                    #pragma unroll
                    for (int k = 0; k < KW; ++k) {
                        if (NPAIR == 2) {
                            unsigned long long w01, w23;
                            asm("ld.shared.v2.b64 {%0, %1}, [%2];"
                                : "=l"(w01), "=l"(w23)
                                : "r"(wadr + (uint32_t)(k * 128)));
                            #pragma unroll
                            for (int j = 0; j < 8; ++j) {
                                FMA2(acc2[0][j], w01, vp[j + k], acc2[0][j]);
                                FMA2(acc2[1][j], w23, vp[j + k], acc2[1][j]);
                            }
                        } else {
                            unsigned long long w01;
                            asm("ld.shared.b64 %0, [%1];"
                                : "=l"(w01)
                                : "r"(wadr + (uint32_t)(k * 128)));
                            #pragma unroll
                            for (int j = 0; j < 8; ++j)
                                FMA2(acc2[0][j], w01, vp[j + k], acc2[0][j]);
                        }
                    }
                    ci = cin;
                    prow = prown;
                    wadr = sbase +
                        (uint32_t)(ubn * WBLK + rn * WROW + SKF(ubn) + colB) * 4u;
                }
            };

            // ---- phase A: own 32 channels (local, valid pre-barrier) ----
            conv_run(co0 + ciq, CNTA);

            CLUSTER_WAIT();          // peers' prev-row STGs now visible

            // reload peers' 96 channels of row pr via cp.async
            {
                const size_t prOff = (size_t)pr * L;
                for (int idx = tid; idx < 96 * L4; idx += BLOCK) {
                    int ch = idx / L4, j = idx - ch * L4;
                    int c  = (co0 + 32 + ch) & (C_ - 1);
                    CP_ASYNC16(
                        sbase + (uint32_t)(WFL + PP_OFF(c) + 4 + 4 * j) * 4u,
                        outB + (size_t)c * CHS + prOff + 4 * j);
                }
                CP_ASYNC_COMMIT();
                CP_ASYNC_WAIT0();
                __syncthreads();
            }

            // ---- phase B: peers' 96 channels ----
            conv_run((co0 + 32 + ciq) & (C_ - 1), CNTB);

            // unpack packed accumulators -> accf[a][j]
            float accf[COW][8];
            #pragma unroll
            for (int pr2 = 0; pr2 < NPAIR; ++pr2)
                #pragma unroll
                for (int j = 0; j < 8; ++j)
                    UNPACK2(accf[2 * pr2][j], accf[2 * pr2 + 1][j], acc2[pr2][j]);

            if (CI_SPLIT > 1) {      // butterfly: all ciq lanes get full sums
                #pragma unroll
                for (int a = 0; a < COW; ++a)
                    #pragma unroll
                    for (int j = 0; j < 8; ++j) {
                        float s = accf[a][j];
                        #pragma unroll
                        for (int off = CI_SPLIT >> 1; off > 0; off >>= 1)
                            s += __shfl_xor_sync(0xffffffffu, s, off);
                        accf[a][j] = s;
                    }
            }

            // epilogue spread across ciq lanes: each writes one float4
            float4 rO;
            if (doO) {
                const float* xr = &xsm[(colB + aa) * L + w0 + 4 * hh];
                const float4 x0 = *reinterpret_cast<const float4*>(xr);
                rO.x = x0.x + fmaxf(accf[aa][4 * hh + 0], 0.0f);
                rO.y = x0.y + fmaxf(accf[aa][4 * hh + 1], 0.0f);
                rO.z = x0.z + fmaxf(accf[aa][4 * hh + 2], 0.0f);
                rO.w = x0.w + fmaxf(accf[aa][4 * hh + 3], 0.0f);
                *reinterpret_cast<float4*>(
                    outB + (size_t)(co0 + colB + aa) * CHS + rowOff + w0 + 4 * hh)
                    = rO;
            }

            // transposed VALUES computed pre-arrive (xsm stable)
            float rT[4];
            if (doT) {
                #pragma unroll
                for (int m = 0; m < 4; ++m) {
                    const int mm = 4 * tl + m;
                    const int a = mm >> 3, j = mm & 7;
                    if (w0 + j < L)
                        rT[m] = xsm[(colB + a) * L + w0 + j] +
                                fmaxf(accf[a][j], 0.0f);
                }
            }

            // prefetch next step's skip-connection row BEFORE the barrier
            float4 xn;
            const bool xnv = (tid < 32 * L4) && (step + 1 < S);
            int xc = tid / L4, xj = tid - xc * L4;
            if (xnv)
                xn = *reinterpret_cast<const float4*>(
                    inB + (size_t)(co0 + xc) * CHS + (size_t)pn * L + 4 * xj);

            if (step + 1 < S) CLUSTER_ARRIVE();   // release our row to peers
            __syncthreads();      // all pp/xsm reads done before overwrite

            // -- deferred local work (hidden before next step's wait) --
            if (doO)
                *reinterpret_cast<float4*>(
                    &pp[PP_OFF(co0 + colB + aa) + 4 + w0 + 4 * hh]) = rO;
            if (doT) {
                #pragma unroll
                for (int m = 0; m < 4; ++m) {
                    const int mm = 4 * tl + m;
                    const int a = mm >> 3, j = mm & 7;
                    if (w0 + j < L)
                        toutB[(size_t)(co0 + colB + a) * CHS +
                              (size_t)(w0 + j) * S + p] = rT[m];
                }
            }
            if (xnv)
                *reinterpret_cast<float4*>(&xsm[xc * L + 4 * xj]) = xn;
            __syncthreads();      // own-STS visible to next step's phase A
        }
    }
    #undef PP_OFF
    #undef W_OFF
}

extern "C" void kernel_launch(void* const* d_in, const int* in_sizes, int n_in,
                              void* d_out, int out_size)
{
    const float* x    = (const float*)d_in[0];
    const float* w_ud = (const float*)d_in[1];
    const float* w_du = (const float*)d_in[2];
    const float* w_lr = (const float*)d_in[3];
    const float* w_rl = (const float*)d_in[4];
    float* out = (float*)d_out;

    float *b0, *b1, *b2;
    cudaGetSymbolAddress((void**)&b0, g_buf0);
    cudaGetSymbolAddress((void**)&b1, g_buf1);
    cudaGetSymbolAddress((void**)&b2, g_buf2);

    constexpr int WROW = KW * 32 + 4;
    constexpr int WBLK = 16 * WROW + 32;
    constexpr int WFL  = 8 * WBLK + 32;
    constexpr int SM_V = (WFL + 8 * (16 * (W_ + 16) + 32) + 32 + 32 * W_) * 4;
    constexpr int SM_H = (WFL + 8 * (16 * (H_ + 16) + 32) + 32 + 32 * H_) * 4;

    // vertical:  co2 x w8: 13 wt x 16 cot x 4 ciq = 832 thr (26 warps)
    // horizontal: co2 x w8: 5 wt x 16 cot x 8 ciq = 640 thr (20 warps)
    cudaFuncSetAttribute(scnn_pass<H_, W_, 4, 832, 2, false>,
                         cudaFuncAttributeMaxDynamicSharedMemorySize, SM_V);
    cudaFuncSetAttribute(scnn_pass<H_, W_, 4, 832, 2, true>,
                         cudaFuncAttributeMaxDynamicSharedMemorySize, SM_V);
    cudaFuncSetAttribute(scnn_pass<W_, H_, 8, 640, 2, false>,
                         cudaFuncAttributeMaxDynamicSharedMemorySize, SM_H);
    cudaFuncSetAttribute(scnn_pass<W_, H_, 8, 640, 2, true>,
                         cudaFuncAttributeMaxDynamicSharedMemorySize, SM_H);

    const dim3 grid(4, B_, 1);

    // pass 1: down  (scan H, conv along W), layout [B,C,H,W]
    scnn_pass<H_, W_, 4, 832, 2, false><<<grid, 832, SM_V>>>(
        x,  w_ud, b0, 0, nullptr);
    // pass 2: up — also emits [B,C,W,H]-transposed copy into b2
    scnn_pass<H_, W_, 4, 832, 2, true><<<grid, 832, SM_V>>>(
        b0, w_du, b1, 1, b2);
    // pass 3: left->right (scan W, conv along H), layout [B,C,W,H]
    scnn_pass<W_, H_, 8, 640, 2, false><<<grid, 640, SM_H>>>(
        b2, w_lr, b0, 0, nullptr);
    // pass 4: right->left — transposed copy goes straight to d_out ([B,C,H,W])
    scnn_pass<W_, H_, 8, 640, 2, true><<<grid, 640, SM_H>>>(
        b0, w_rl, b1, 1, out);
}